// round 16
// baseline (speedup 1.0000x reference)
#include <cuda_runtime.h>
#include <cuda_bf16.h>
#include <math.h>
#include <stdint.h>

#define L_LAYERS 6
#define BATCH    4
#define SEQ      1024
#define HID      768
#define NHEAD    12
#define HDIM     64
#define FFDIM    3072
#define MTOK     (BATCH*SEQ)      // 4096 tokens
#define NBH      (BATCH*NHEAD)    // 48
#define FBM      128              // flash: query rows per CTA
#define FBN      64               // flash: keys per iteration
#define QKVD     2304             // fused QKV output width

typedef __nv_bfloat16 bf16;

// ---------------------------------------------------------------------------
// Scratch (device globals)
// ---------------------------------------------------------------------------
__device__ float g_x   [MTOK*HID];
__device__ float g_y   [MTOK*HID];
__device__ float g_attn[MTOK*HID];
__device__ float g_y2  [MTOK*HID];

__device__ bf16 g_xh[MTOK*HID],   g_xl[MTOK*HID];
__device__ bf16 g_qkvh[MTOK*QKVD],g_qkvl[MTOK*QKVD]; // fused QKV split
__device__ bf16 g_vth[MTOK*HID],  g_vtl[MTOK*HID];   // V^T per batch [HID][SEQ]
__device__ bf16 g_ch[MTOK*HID],   g_cl[MTOK*HID];    // ctx split
__device__ bf16 g_ah[MTOK*HID],   g_al[MTOK*HID];    // LN1 split
__device__ bf16 g_fh[MTOK*FFDIM], g_fl[MTOK*FFDIM];  // FF hidden split

// weights split, transposed [N,K]
__device__ bf16  g_qkvwh[QKVD*HID], g_qkvwl[QKVD*HID];
__device__ float g_qkvb[QKVD];
__device__ bf16  g_awh[HID*HID],   g_awl[HID*HID];
__device__ bf16  g_f1h[HID*FFDIM], g_f1l[HID*FFDIM];
__device__ bf16  g_f2h[FFDIM*HID], g_f2l[FFDIM*HID];

__device__ __forceinline__ void split2(float v, bf16& h, bf16& l)
{
    h = __float2bfloat16_rn(v);
    l = __float2bfloat16_rn(v - __bfloat162float(h));
}

__device__ __forceinline__ uint32_t pack_bf2(bf16 a, bf16 b)
{
    __nv_bfloat162 t(a, b);
    return *reinterpret_cast<uint32_t*>(&t);
}

// ---------------------------------------------------------------------------
// Split helpers
// ---------------------------------------------------------------------------
__global__ __launch_bounds__(256)
void split_act(const float* __restrict__ x, bf16* __restrict__ h,
               bf16* __restrict__ l, int n)
{
    int i = (blockIdx.x * 256 + threadIdx.x) * 4;
    if (i >= n) return;
    float4 v = *reinterpret_cast<const float4*>(x + i);
    bf16 h0, h1, h2, h3, l0, l1, l2, l3;
    split2(v.x, h0, l0); split2(v.y, h1, l1);
    split2(v.z, h2, l2); split2(v.w, h3, l3);
    __nv_bfloat162* hp = reinterpret_cast<__nv_bfloat162*>(h + i);
    __nv_bfloat162* lp = reinterpret_cast<__nv_bfloat162*>(l + i);
    hp[0] = __nv_bfloat162(h0, h1); hp[1] = __nv_bfloat162(h2, h3);
    lp[0] = __nv_bfloat162(l0, l1); lp[1] = __nv_bfloat162(l2, l3);
}

// W[K,N] row-major -> split, transposed to [N,K]
__global__ __launch_bounds__(256)
void split_wT(const float* __restrict__ W, bf16* __restrict__ hT,
              bf16* __restrict__ lT, int K, int N)
{
    int idx = blockIdx.x * 256 + threadIdx.x;
    if (idx >= K * N) return;
    int k = idx / N, n = idx - k * N;
    bf16 h, l;
    split2(W[idx], h, l);
    hT[(size_t)n * K + k] = h;
    lT[(size_t)n * K + k] = l;
}

// q/k/v weights [768,768] -> combined transposed [2304][768] + combined bias
__global__ __launch_bounds__(256)
void split_wT3(const float* __restrict__ Wq, const float* __restrict__ Wk,
               const float* __restrict__ Wv,
               const float* __restrict__ bq, const float* __restrict__ bk,
               const float* __restrict__ bv,
               bf16* __restrict__ hT, bf16* __restrict__ lT,
               float* __restrict__ bias)
{
    int idx = blockIdx.x * 256 + threadIdx.x;
    if (idx < QKVD) {
        bias[idx] = (idx < HID) ? bq[idx]
                  : (idx < 2 * HID) ? bk[idx - HID] : bv[idx - 2 * HID];
    }
    if (idx >= HID * HID) return;
    int k = idx / HID, n = idx - k * HID;
    bf16 h, l;
    split2(Wq[idx], h, l);
    hT[(size_t)n * HID + k] = h;               lT[(size_t)n * HID + k] = l;
    split2(Wk[idx], h, l);
    hT[(size_t)(n + HID) * HID + k] = h;       lT[(size_t)(n + HID) * HID + k] = l;
    split2(Wv[idx], h, l);
    hT[(size_t)(n + 2 * HID) * HID + k] = h;   lT[(size_t)(n + 2 * HID) * HID + k] = l;
}

// transpose split V from qkv buffer (cols [1536,2304)) -> [B][HID][SEQ]
__global__ __launch_bounds__(256)
void trans_v(const bf16* __restrict__ qkvh, const bf16* __restrict__ qkvl,
             bf16* __restrict__ th, bf16* __restrict__ tl)
{
    __shared__ bf16 t0[32][33];
    __shared__ bf16 t1[32][33];
    const int b  = blockIdx.z;
    const int s0 = blockIdx.x * 32;
    const int d0 = blockIdx.y * 32;
    const int x  = threadIdx.x;     // 0..31
    const int y  = threadIdx.y;     // 0..7
#pragma unroll
    for (int i = 0; i < 32; i += 8) {
        size_t g = ((size_t)b * SEQ + s0 + y + i) * QKVD + 2 * HID + d0 + x;
        t0[y + i][x] = qkvh[g];
        t1[y + i][x] = qkvl[g];
    }
    __syncthreads();
#pragma unroll
    for (int i = 0; i < 32; i += 8) {
        size_t o = ((size_t)b * HID + d0 + y + i) * SEQ + s0 + x;
        th[o] = t0[x][y + i];
        tl[o] = t1[x][y + i];
    }
}

// ---------------------------------------------------------------------------
// mma.sync m16n8k16 bf16 -> fp32  and ldmatrix helper
// ---------------------------------------------------------------------------
__device__ __forceinline__ void mma16816(float* c, const uint32_t* a, const uint32_t* b)
{
    asm("mma.sync.aligned.m16n8k16.row.col.f32.bf16.bf16.f32 "
        "{%0,%1,%2,%3}, {%4,%5,%6,%7}, {%8,%9}, {%0,%1,%2,%3};"
        : "+f"(c[0]), "+f"(c[1]), "+f"(c[2]), "+f"(c[3])
        : "r"(a[0]), "r"(a[1]), "r"(a[2]), "r"(a[3]), "r"(b[0]), "r"(b[1]));
}

__device__ __forceinline__ void ldm_x4(uint32_t* r, const void* smem_ptr)
{
    uint32_t addr = (uint32_t)__cvta_generic_to_shared(smem_ptr);
    asm volatile("ldmatrix.sync.aligned.m8n8.x4.shared.b16 {%0,%1,%2,%3}, [%4];"
                 : "=r"(r[0]), "=r"(r[1]), "=r"(r[2]), "=r"(r[3]) : "r"(addr));
}

// ---------------------------------------------------------------------------
// Dense tensor-core GEMM (3-term split): C = A@W + bias (+res)(+GELU)
// A:[M,K] split pair, W:[N,K] split pair. BM=BN=128, BK=16, 8 warps (2x4).
// Fragment loads via ldmatrix.x4.
// ---------------------------------------------------------------------------
template<int ACT, bool HASRES, bool SPLITOUT>
__global__ __launch_bounds__(256, 1)
void tc_gemm(const bf16* __restrict__ Ah, const bf16* __restrict__ Al,
             const bf16* __restrict__ WhT, const bf16* __restrict__ WlT,
             const float* __restrict__ bias, const float* __restrict__ res,
             float* __restrict__ C, bf16* __restrict__ Oh, bf16* __restrict__ Ol,
             int Ndim, int Kdim)
{
    __shared__ __align__(16) bf16 sAh[2][128][24];
    __shared__ __align__(16) bf16 sAl[2][128][24];
    __shared__ __align__(16) bf16 sBh[2][128][24];
    __shared__ __align__(16) bf16 sBl[2][128][24];

    const int tid  = threadIdx.x;
    const int row0 = blockIdx.y * 128;
    const int col0 = blockIdx.x * 128;
    const int lrow = tid >> 1;
    const int kofs = (tid & 1) * 8;

    const bf16* pAh = Ah  + (size_t)(row0 + lrow) * Kdim + kofs;
    const bf16* pAl = Al  + (size_t)(row0 + lrow) * Kdim + kofs;
    const bf16* pBh = WhT + (size_t)(col0 + lrow) * Kdim + kofs;
    const bf16* pBl = WlT + (size_t)(col0 + lrow) * Kdim + kofs;

    const int wid  = tid >> 5;
    const int m0   = (wid & 1) * 64;
    const int n0   = (wid >> 1) * 32;
    const int lane = tid & 31;
    const int gg   = lane >> 2;
    const int tg   = lane & 3;

    // ldmatrix address selectors
    const int a_row = (lane & 7) + ((lane >> 3) & 1) * 8;  // 0..15 within m-tile
    const int a_col = (lane >> 4) * 8;                      // 0 or 8
    const int b_row = (lane & 7) + ((lane >> 4) & 1) * 8;  // 0..15 within n-pair
    const int b_col = ((lane >> 3) & 1) * 8;                // 0 or 8

    float acc[4][4][4];
#pragma unroll
    for (int i = 0; i < 4; i++)
#pragma unroll
        for (int j = 0; j < 4; j++)
#pragma unroll
            for (int t = 0; t < 4; t++) acc[i][j][t] = 0.f;

    {
        uint4 a_h = *reinterpret_cast<const uint4*>(pAh);
        uint4 a_l = *reinterpret_cast<const uint4*>(pAl);
        uint4 b_h = *reinterpret_cast<const uint4*>(pBh);
        uint4 b_l = *reinterpret_cast<const uint4*>(pBl);
        *reinterpret_cast<uint4*>(&sAh[0][lrow][kofs]) = a_h;
        *reinterpret_cast<uint4*>(&sAl[0][lrow][kofs]) = a_l;
        *reinterpret_cast<uint4*>(&sBh[0][lrow][kofs]) = b_h;
        *reinterpret_cast<uint4*>(&sBl[0][lrow][kofs]) = b_l;
    }
    __syncthreads();

    int s = 0;
    for (int k0 = 0; k0 < Kdim; k0 += 16) {
        const bool has_next = (k0 + 16 < Kdim);
        uint4 nAh, nAl, nBh, nBl;
        if (has_next) {
            nAh = *reinterpret_cast<const uint4*>(pAh + k0 + 16);
            nAl = *reinterpret_cast<const uint4*>(pAl + k0 + 16);
            nBh = *reinterpret_cast<const uint4*>(pBh + k0 + 16);
            nBl = *reinterpret_cast<const uint4*>(pBl + k0 + 16);
        }

        uint32_t afh[4][4], afl[4][4], bfh[4][2], bfl[4][2];
#pragma unroll
        for (int i = 0; i < 4; i++) {
            ldm_x4(afh[i], &sAh[s][m0 + i * 16 + a_row][a_col]);
            ldm_x4(afl[i], &sAl[s][m0 + i * 16 + a_row][a_col]);
        }
#pragma unroll
        for (int jp = 0; jp < 2; jp++) {
            uint32_t t4[4];
            ldm_x4(t4, &sBh[s][n0 + jp * 16 + b_row][b_col]);
            bfh[2 * jp][0] = t4[0]; bfh[2 * jp][1] = t4[1];
            bfh[2 * jp + 1][0] = t4[2]; bfh[2 * jp + 1][1] = t4[3];
            ldm_x4(t4, &sBl[s][n0 + jp * 16 + b_row][b_col]);
            bfl[2 * jp][0] = t4[0]; bfl[2 * jp][1] = t4[1];
            bfl[2 * jp + 1][0] = t4[2]; bfl[2 * jp + 1][1] = t4[3];
        }

#pragma unroll
        for (int i = 0; i < 4; i++)
#pragma unroll
            for (int j = 0; j < 4; j++) {
                mma16816(acc[i][j], afh[i], bfh[j]);
                mma16816(acc[i][j], afh[i], bfl[j]);
                mma16816(acc[i][j], afl[i], bfh[j]);
            }

        if (has_next) {
            const int ns = s ^ 1;
            *reinterpret_cast<uint4*>(&sAh[ns][lrow][kofs]) = nAh;
            *reinterpret_cast<uint4*>(&sAl[ns][lrow][kofs]) = nAl;
            *reinterpret_cast<uint4*>(&sBh[ns][lrow][kofs]) = nBh;
            *reinterpret_cast<uint4*>(&sBl[ns][lrow][kofs]) = nBl;
            __syncthreads();
        }
        s ^= 1;
    }

#pragma unroll
    for (int i = 0; i < 4; i++) {
        const int r_lo = row0 + m0 + i * 16 + gg;
        const int r_hi = r_lo + 8;
#pragma unroll
        for (int j = 0; j < 4; j++) {
            const int c = col0 + n0 + j * 8 + 2 * tg;
            float2 b2 = *reinterpret_cast<const float2*>(bias + c);
            float v0 = acc[i][j][0] + b2.x;
            float v1 = acc[i][j][1] + b2.y;
            float v2 = acc[i][j][2] + b2.x;
            float v3 = acc[i][j][3] + b2.y;
            if (HASRES) {
                float2 r0 = *reinterpret_cast<const float2*>(res + (size_t)r_lo * Ndim + c);
                float2 r1 = *reinterpret_cast<const float2*>(res + (size_t)r_hi * Ndim + c);
                v0 += r0.x; v1 += r0.y; v2 += r1.x; v3 += r1.y;
            }
            if (ACT == 1) {
                v0 = 0.5f * v0 * (1.f + erff(v0 * 0.7071067811865475f));
                v1 = 0.5f * v1 * (1.f + erff(v1 * 0.7071067811865475f));
                v2 = 0.5f * v2 * (1.f + erff(v2 * 0.7071067811865475f));
                v3 = 0.5f * v3 * (1.f + erff(v3 * 0.7071067811865475f));
            }
            if (SPLITOUT) {
                bf16 h0, h1, h2, h3, l0, l1, l2, l3;
                split2(v0, h0, l0); split2(v1, h1, l1);
                split2(v2, h2, l2); split2(v3, h3, l3);
                *reinterpret_cast<__nv_bfloat162*>(Oh + (size_t)r_lo * Ndim + c) = __nv_bfloat162(h0, h1);
                *reinterpret_cast<__nv_bfloat162*>(Oh + (size_t)r_hi * Ndim + c) = __nv_bfloat162(h2, h3);
                *reinterpret_cast<__nv_bfloat162*>(Ol + (size_t)r_lo * Ndim + c) = __nv_bfloat162(l0, l1);
                *reinterpret_cast<__nv_bfloat162*>(Ol + (size_t)r_hi * Ndim + c) = __nv_bfloat162(l2, l3);
            } else {
                *reinterpret_cast<float2*>(C + (size_t)r_lo * Ndim + c) = make_float2(v0, v1);
                *reinterpret_cast<float2*>(C + (size_t)r_hi * Ndim + c) = make_float2(v2, v3);
            }
        }
    }
}

// ---------------------------------------------------------------------------
// Fused flash attention (per (b,h)): ctx = softmax(QK^T/8 + mask) @ V
// K/V fragment loads via ldmatrix.x4 (row stride 144B: phases cover all 32
// banks exactly once; conflict-free).
// ---------------------------------------------------------------------------
__global__ __launch_bounds__(256, 1)
void flash_attn(const bf16* __restrict__ qkvh, const bf16* __restrict__ qkvl,
                const bf16* __restrict__ vth, const bf16* __restrict__ vtl,
                const float* __restrict__ mask,
                bf16* __restrict__ ch, bf16* __restrict__ cl)
{
    __shared__ __align__(16) bf16 sKh[FBN][72], sKl[FBN][72];     // [key][d]
    __shared__ __align__(16) bf16 sVh[HDIM][72], sVl[HDIM][72];   // [d][key]
    __shared__ float sMask[SEQ];

    const int z = blockIdx.y;
    const int b = z / NHEAD, h = z % NHEAD;
    const int row0 = blockIdx.x * FBM;
    const int tid  = threadIdx.x;
    const int wid  = tid >> 5;
    const int lane = tid & 31;
    const int gg   = lane >> 2;
    const int tg   = lane & 3;
    const int mrow = row0 + wid * 16;   // warp's first query row
    const size_t hoff = (size_t)h * HDIM;

    // ldmatrix B-operand selectors
    const int b_row = (lane & 7) + ((lane >> 4) & 1) * 8;  // 0..15
    const int b_col = ((lane >> 3) & 1) * 8;                // 0 or 8

    for (int i = tid; i < SEQ; i += 256)
        sMask[i] = mask[(size_t)b * SEQ + i];

    // Q fragments (4 k-steps), loaded directly from gmem
    uint32_t qfh[4][4], qfl[4][4];
#pragma unroll
    for (int kk = 0; kk < 4; kk++) {
        const size_t r0 = ((size_t)(b * SEQ + mrow + gg))     * QKVD + hoff + kk * 16 + 2 * tg;
        const size_t r1 = ((size_t)(b * SEQ + mrow + 8 + gg)) * QKVD + hoff + kk * 16 + 2 * tg;
        qfh[kk][0] = *reinterpret_cast<const uint32_t*>(qkvh + r0);
        qfh[kk][1] = *reinterpret_cast<const uint32_t*>(qkvh + r1);
        qfh[kk][2] = *reinterpret_cast<const uint32_t*>(qkvh + r0 + 8);
        qfh[kk][3] = *reinterpret_cast<const uint32_t*>(qkvh + r1 + 8);
        qfl[kk][0] = *reinterpret_cast<const uint32_t*>(qkvl + r0);
        qfl[kk][1] = *reinterpret_cast<const uint32_t*>(qkvl + r1);
        qfl[kk][2] = *reinterpret_cast<const uint32_t*>(qkvl + r0 + 8);
        qfl[kk][3] = *reinterpret_cast<const uint32_t*>(qkvl + r1 + 8);
    }

    float o[8][4];
#pragma unroll
    for (int j = 0; j < 8; j++)
#pragma unroll
        for (int t = 0; t < 4; t++) o[j][t] = 0.f;
    float m0 = -1e30f, m1 = -1e30f, l0 = 0.f, l1 = 0.f;

    const int lrow = tid >> 2;        // 0..63
    const int lc   = (tid & 3) * 16;  // 0,16,32,48

    for (int k0 = 0; k0 < SEQ; k0 += FBN) {
        // stage K block (from qkv cols 768+h*64) and V^T block
        {
            const size_t gk = ((size_t)(b * SEQ + k0 + lrow)) * QKVD + HID + hoff + lc;
            *reinterpret_cast<uint4*>(&sKh[lrow][lc])     = *reinterpret_cast<const uint4*>(qkvh + gk);
            *reinterpret_cast<uint4*>(&sKh[lrow][lc + 8]) = *reinterpret_cast<const uint4*>(qkvh + gk + 8);
            *reinterpret_cast<uint4*>(&sKl[lrow][lc])     = *reinterpret_cast<const uint4*>(qkvl + gk);
            *reinterpret_cast<uint4*>(&sKl[lrow][lc + 8]) = *reinterpret_cast<const uint4*>(qkvl + gk + 8);
            const size_t gv = ((size_t)b * HID + hoff + lrow) * SEQ + k0 + lc;
            *reinterpret_cast<uint4*>(&sVh[lrow][lc])     = *reinterpret_cast<const uint4*>(vth + gv);
            *reinterpret_cast<uint4*>(&sVh[lrow][lc + 8]) = *reinterpret_cast<const uint4*>(vth + gv + 8);
            *reinterpret_cast<uint4*>(&sVl[lrow][lc])     = *reinterpret_cast<const uint4*>(vtl + gv);
            *reinterpret_cast<uint4*>(&sVl[lrow][lc + 8]) = *reinterpret_cast<const uint4*>(vtl + gv + 8);
        }
        __syncthreads();

        // S = Q K^T
        float S[8][4];
#pragma unroll
        for (int j = 0; j < 8; j++)
#pragma unroll
            for (int t = 0; t < 4; t++) S[j][t] = 0.f;

#pragma unroll
        for (int kk = 0; kk < 4; kk++) {
            uint32_t bh[8][2], bl[8][2];
#pragma unroll
            for (int jp = 0; jp < 4; jp++) {
                uint32_t t4[4];
                ldm_x4(t4, &sKh[jp * 16 + b_row][kk * 16 + b_col]);
                bh[2 * jp][0] = t4[0]; bh[2 * jp][1] = t4[1];
                bh[2 * jp + 1][0] = t4[2]; bh[2 * jp + 1][1] = t4[3];
                ldm_x4(t4, &sKl[jp * 16 + b_row][kk * 16 + b_col]);
                bl[2 * jp][0] = t4[0]; bl[2 * jp][1] = t4[1];
                bl[2 * jp + 1][0] = t4[2]; bl[2 * jp + 1][1] = t4[3];
            }
#pragma unroll
            for (int j = 0; j < 8; j++) {
                mma16816(S[j], qfh[kk], bh[j]);
                mma16816(S[j], qfh[kk], bl[j]);
                mma16816(S[j], qfl[kk], bh[j]);
            }
        }

        // scale + additive mask
#pragma unroll
        for (int j = 0; j < 8; j++) {
            const float mk0 = sMask[k0 + j * 8 + 2 * tg];
            const float mk1 = sMask[k0 + j * 8 + 2 * tg + 1];
            S[j][0] = S[j][0] * 0.125f + mk0;
            S[j][1] = S[j][1] * 0.125f + mk1;
            S[j][2] = S[j][2] * 0.125f + mk0;
            S[j][3] = S[j][3] * 0.125f + mk1;
        }

        // online softmax
        float mx0 = -1e30f, mx1 = -1e30f;
#pragma unroll
        for (int j = 0; j < 8; j++) {
            mx0 = fmaxf(mx0, fmaxf(S[j][0], S[j][1]));
            mx1 = fmaxf(mx1, fmaxf(S[j][2], S[j][3]));
        }
        mx0 = fmaxf(mx0, __shfl_xor_sync(0xffffffffu, mx0, 1));
        mx0 = fmaxf(mx0, __shfl_xor_sync(0xffffffffu, mx0, 2));
        mx1 = fmaxf(mx1, __shfl_xor_sync(0xffffffffu, mx1, 1));
        mx1 = fmaxf(mx1, __shfl_xor_sync(0xffffffffu, mx1, 2));

        const float mn0 = fmaxf(m0, mx0);
        const float mn1 = fmaxf(m1, mx1);
        const float a0 = __expf(m0 - mn0);
        const float a1 = __expf(m1 - mn1);
        m0 = mn0; m1 = mn1;

        float s0 = 0.f, s1 = 0.f;
#pragma unroll
        for (int j = 0; j < 8; j++) {
            S[j][0] = __expf(S[j][0] - m0); s0 += S[j][0];
            S[j][1] = __expf(S[j][1] - m0); s0 += S[j][1];
            S[j][2] = __expf(S[j][2] - m1); s1 += S[j][2];
            S[j][3] = __expf(S[j][3] - m1); s1 += S[j][3];
        }
        s0 += __shfl_xor_sync(0xffffffffu, s0, 1);
        s0 += __shfl_xor_sync(0xffffffffu, s0, 2);
        s1 += __shfl_xor_sync(0xffffffffu, s1, 1);
        s1 += __shfl_xor_sync(0xffffffffu, s1, 2);
        l0 = l0 * a0 + s0;
        l1 = l1 * a1 + s1;

#pragma unroll
        for (int j = 0; j < 8; j++) {
            o[j][0] *= a0; o[j][1] *= a0;
            o[j][2] *= a1; o[j][3] *= a1;
        }

        // P accumulators -> A fragments, split bf16
        uint32_t pfh[4][4], pfl[4][4];
#pragma unroll
        for (int kk = 0; kk < 4; kk++) {
            bf16 h0, h1, lo0, lo1;
            split2(S[2 * kk][0], h0, lo0); split2(S[2 * kk][1], h1, lo1);
            pfh[kk][0] = pack_bf2(h0, h1); pfl[kk][0] = pack_bf2(lo0, lo1);
            split2(S[2 * kk][2], h0, lo0); split2(S[2 * kk][3], h1, lo1);
            pfh[kk][1] = pack_bf2(h0, h1); pfl[kk][1] = pack_bf2(lo0, lo1);
            split2(S[2 * kk + 1][0], h0, lo0); split2(S[2 * kk + 1][1], h1, lo1);
            pfh[kk][2] = pack_bf2(h0, h1); pfl[kk][2] = pack_bf2(lo0, lo1);
            split2(S[2 * kk + 1][2], h0, lo0); split2(S[2 * kk + 1][3], h1, lo1);
            pfh[kk][3] = pack_bf2(h0, h1); pfl[kk][3] = pack_bf2(lo0, lo1);
        }

        // O += P V
#pragma unroll
        for (int kk = 0; kk < 4; kk++) {
            uint32_t bh[8][2], bl[8][2];
#pragma unroll
            for (int jp = 0; jp < 4; jp++) {
                uint32_t t4[4];
                ldm_x4(t4, &sVh[jp * 16 + b_row][kk * 16 + b_col]);
                bh[2 * jp][0] = t4[0]; bh[2 * jp][1] = t4[1];
                bh[2 * jp + 1][0] = t4[2]; bh[2 * jp + 1][1] = t4[3];
                ldm_x4(t4, &sVl[jp * 16 + b_row][kk * 16 + b_col]);
                bl[2 * jp][0] = t4[0]; bl[2 * jp][1] = t4[1];
                bl[2 * jp + 1][0] = t4[2]; bl[2 * jp + 1][1] = t4[3];
            }
#pragma unroll
            for (int jd = 0; jd < 8; jd++) {
                mma16816(o[jd], pfh[kk], bh[jd]);
                mma16816(o[jd], pfh[kk], bl[jd]);
                mma16816(o[jd], pfl[kk], bh[jd]);
            }
        }
        __syncthreads();
    }

    // epilogue: normalize, split-store ctx
    const float inv0 = 1.f / l0;
    const float inv1 = 1.f / l1;
    const size_t r_lo = (size_t)(b * SEQ) + mrow + gg;
    const size_t r_hi = r_lo + 8;
#pragma unroll
    for (int jd = 0; jd < 8; jd++) {
        const size_t c = hoff + jd * 8 + 2 * tg;
        float v0 = o[jd][0] * inv0, v1 = o[jd][1] * inv0;
        float v2 = o[jd][2] * inv1, v3 = o[jd][3] * inv1;
        bf16 h0, h1, h2, h3, lo0, lo1, lo2, lo3;
        split2(v0, h0, lo0); split2(v1, h1, lo1);
        split2(v2, h2, lo2); split2(v3, h3, lo3);
        *reinterpret_cast<__nv_bfloat162*>(ch + r_lo * HID + c) = __nv_bfloat162(h0, h1);
        *reinterpret_cast<__nv_bfloat162*>(ch + r_hi * HID + c) = __nv_bfloat162(h2, h3);
        *reinterpret_cast<__nv_bfloat162*>(cl + r_lo * HID + c) = __nv_bfloat162(lo0, lo1);
        *reinterpret_cast<__nv_bfloat162*>(cl + r_hi * HID + c) = __nv_bfloat162(lo2, lo3);
    }
}

// ---------------------------------------------------------------------------
// LayerNorm over HID=768, bf16 split outputs fused.
// ---------------------------------------------------------------------------
__global__ __launch_bounds__(256)
void layernorm_split(const float* __restrict__ x, const float* __restrict__ gam,
                     const float* __restrict__ bet, float* __restrict__ out,
                     bf16* __restrict__ oh, bf16* __restrict__ ol)
{
    const int row = blockIdx.x;
    const float* xr = x + (size_t)row * HID;
    const int tid = threadIdx.x;
    __shared__ float rs_[8], rq_[8];

    float v0 = xr[tid], v1 = xr[tid + 256], v2 = xr[tid + 512];
    float s  = v0 + v1 + v2;
    float sq = v0 * v0 + v1 * v1 + v2 * v2;
#pragma unroll
    for (int o = 16; o; o >>= 1) {
        s  += __shfl_xor_sync(0xffffffffu, s,  o);
        sq += __shfl_xor_sync(0xffffffffu, sq, o);
    }
    if ((tid & 31) == 0) { rs_[tid >> 5] = s; rq_[tid >> 5] = sq; }
    __syncthreads();
    float ts = 0.f, tq = 0.f;
#pragma unroll
    for (int i = 0; i < 8; i++) { ts += rs_[i]; tq += rq_[i]; }
    const float mean = ts * (1.f / HID);
    const float var  = tq * (1.f / HID) - mean * mean;
    const float rstd = rsqrtf(var + 1e-5f);

    float* o = out + (size_t)row * HID;
    float r0 = (v0 - mean) * rstd * gam[tid]       + bet[tid];
    float r1 = (v1 - mean) * rstd * gam[tid + 256] + bet[tid + 256];
    float r2 = (v2 - mean) * rstd * gam[tid + 512] + bet[tid + 512];
    o[tid] = r0; o[tid + 256] = r1; o[tid + 512] = r2;

    bf16 h, l;
    split2(r0, h, l); oh[(size_t)row * HID + tid]       = h; ol[(size_t)row * HID + tid]       = l;
    split2(r1, h, l); oh[(size_t)row * HID + tid + 256] = h; ol[(size_t)row * HID + tid + 256] = l;
    split2(r2, h, l); oh[(size_t)row * HID + tid + 512] = h; ol[(size_t)row * HID + tid + 512] = l;
}

// ---------------------------------------------------------------------------
// Launcher
// ---------------------------------------------------------------------------
extern "C" void kernel_launch(void* const* d_in, const int* in_sizes, int n_in,
                              void* d_out, int out_size)
{
    (void)in_sizes; (void)n_in; (void)out_size;
    const float* hs    = (const float*)d_in[0];
    const float* mask  = (const float*)d_in[1];
    const float* q_w   = (const float*)d_in[2];
    const float* q_b   = (const float*)d_in[3];
    const float* k_w   = (const float*)d_in[4];
    const float* k_b   = (const float*)d_in[5];
    const float* v_w   = (const float*)d_in[6];
    const float* v_b   = (const float*)d_in[7];
    const float* ao_w  = (const float*)d_in[8];
    const float* ao_b  = (const float*)d_in[9];
    const float* ln1_g = (const float*)d_in[10];
    const float* ln1_b = (const float*)d_in[11];
    const float* ff1_w = (const float*)d_in[12];
    const float* ff1_b = (const float*)d_in[13];
    const float* ff2_w = (const float*)d_in[14];
    const float* ff2_b = (const float*)d_in[15];
    const float* ln2_g = (const float*)d_in[16];
    const float* ln2_b = (const float*)d_in[17];
    float* out = (float*)d_out;

    float *x, *y, *attn, *y2, *qkvb;
    cudaGetSymbolAddress((void**)&x,    g_x);
    cudaGetSymbolAddress((void**)&y,    g_y);
    cudaGetSymbolAddress((void**)&attn, g_attn);
    cudaGetSymbolAddress((void**)&y2,   g_y2);
    cudaGetSymbolAddress((void**)&qkvb, g_qkvb);

    bf16 *xh,*xl,*qkvh,*qkvl,*vth,*vtl,*ch,*cl,*ah,*al,*fh,*fl;
    cudaGetSymbolAddress((void**)&xh,   g_xh);   cudaGetSymbolAddress((void**)&xl,   g_xl);
    cudaGetSymbolAddress((void**)&qkvh, g_qkvh); cudaGetSymbolAddress((void**)&qkvl, g_qkvl);
    cudaGetSymbolAddress((void**)&vth,  g_vth);  cudaGetSymbolAddress((void**)&vtl,  g_vtl);
    cudaGetSymbolAddress((void**)&ch,   g_ch);   cudaGetSymbolAddress((void**)&cl,   g_cl);
    cudaGetSymbolAddress((void**)&ah,   g_ah);   cudaGetSymbolAddress((void**)&al,   g_al);
    cudaGetSymbolAddress((void**)&fh,   g_fh);   cudaGetSymbolAddress((void**)&fl,   g_fl);

    bf16 *qkvwh,*qkvwl,*awh,*awl,*f1h,*f1l,*f2h,*f2l;
    cudaGetSymbolAddress((void**)&qkvwh, g_qkvwh); cudaGetSymbolAddress((void**)&qkvwl, g_qkvwl);
    cudaGetSymbolAddress((void**)&awh,   g_awh);   cudaGetSymbolAddress((void**)&awl,   g_awl);
    cudaGetSymbolAddress((void**)&f1h,   g_f1h);   cudaGetSymbolAddress((void**)&f1l,   g_f1l);
    cudaGetSymbolAddress((void**)&f2h,   g_f2h);   cudaGetSymbolAddress((void**)&f2l,   g_f2l);

    const int nHH = HID * HID, nHF = HID * FFDIM;
    split_wT3<<<(nHH + 255) / 256, 256>>>(q_w, k_w, v_w, q_b, k_b, v_b,
                                          qkvwh, qkvwl, qkvb);
    split_wT<<<(nHH + 255) / 256, 256>>>(ao_w, awh, awl, HID, HID);
    split_wT<<<(nHF + 255) / 256, 256>>>(ff1_w, f1h, f1l, HID, FFDIM);
    split_wT<<<(nHF + 255) / 256, 256>>>(ff2_w, f2h, f2l, FFDIM, HID);
    const int nACT = MTOK * HID;
    split_act<<<(nACT / 4 + 255) / 256, 256>>>(hs, xh, xl, nACT);

    const dim3 gQKV(QKVD / 128, MTOK / 128);   // (18, 32)
    const dim3 gH  (HID   / 128, MTOK / 128);
    const dim3 gFF (FFDIM / 128, MTOK / 128);
    const dim3 gFA (SEQ / FBM, NBH);
    const dim3 gVT (SEQ / 32, HID / 32, BATCH);

    for (int l = 0; l < L_LAYERS; l++) {
        const float* xin = (l == 0) ? hs : x;

        tc_gemm<0, false, true><<<gQKV, 256>>>(xh, xl, qkvwh, qkvwl, qkvb, nullptr,
                                               nullptr, qkvh, qkvl, QKVD, HID);
        trans_v<<<gVT, dim3(32, 8)>>>(qkvh, qkvl, vth, vtl);

        flash_attn<<<gFA, 256>>>(qkvh, qkvl, vth, vtl, mask, ch, cl);

        tc_gemm<0, true, false><<<gH, 256>>>(ch, cl, awh, awl, ao_b, xin,
                                             y, nullptr, nullptr, HID, HID);
        layernorm_split<<<MTOK, 256>>>(y, ln1_g, ln1_b, attn, ah, al);

        tc_gemm<1, false, true><<<gFF, 256>>>(ah, al, f1h, f1l, ff1_b, nullptr,
                                              nullptr, fh, fl, FFDIM, HID);
        tc_gemm<0, true, false><<<gH, 256>>>(fh, fl, f2h, f2l, ff2_b, attn,
                                             y2, nullptr, nullptr, HID, FFDIM);

        float* xo = (l == L_LAYERS - 1) ? out : x;
        layernorm_split<<<MTOK, 256>>>(y2, ln2_g, ln2_b, xo, xh, xl);
    }
}